// round 4
// baseline (speedup 1.0000x reference)
#include <cuda_runtime.h>
#include <cuda_bf16.h>
#include <math.h>
#include <cstdint>

// ---------------------------------------------------------------------------
// LSAMCell — Round 4.
//   Split-bf16 GEMM (logical K=6144 = [Ah|Al|Ah] x [Wh;Wh;Wl]) on mma.sync,
//   with deduplicated storage ([Ah|Al], [Wh|Wl], 4096-K each) and BK=64
//   (full 128B-line loads). Rewritten tiny w/r GEMM (no smem, 1 row/block).
// ---------------------------------------------------------------------------

#define B_      1024
#define K_      2048
#define NQKV    3072
#define KPHY    4096               // physical K of dedup A'/W' storage
#define NHEAD_  16
#define DHEAD   64

// GEMM tiling
#define TM      128
#define TN      128
#define BK      64
#define STAGES  3
#define NST     96                 // logical 6144 / 64
#define PITCH   144                // 128B data + 16B skew
#define TILE_B  (128 * PITCH)      // 18432 per operand tile
#define STAGE_BYTES (2 * TILE_B)   // 36864
#define SMEM_TOTAL  (STAGES * STAGE_BYTES)  // 110592

// device scratch (allocation-free rule)
__device__ float g_qkv[B_ * NQKV];                       // 12 MB
__device__ float g_wr [B_ * 32];
__device__ __align__(16) __nv_bfloat16 g_A[B_ * KPHY];   // 8 MB  [Ah | Al]
__device__ __align__(16) __nv_bfloat16 g_W[NQKV * KPHY]; // 25 MB [Wh | Wl]

// ---------------------------------------------------------------------------
__device__ __forceinline__ uint32_t smem_u32(const void* p) {
    uint32_t a;
    asm("{ .reg .u64 t; cvta.to.shared.u64 t, %1; cvt.u32.u64 %0, t; }" : "=r"(a) : "l"(p));
    return a;
}
__device__ __forceinline__ void cp16(uint32_t dst, const void* src) {
    asm volatile("cp.async.cg.shared.global [%0], [%1], 16;" :: "r"(dst), "l"(src));
}
#define CP_COMMIT() asm volatile("cp.async.commit_group;" ::: "memory")
#define CP_WAIT(n)  asm volatile("cp.async.wait_group %0;" :: "n"(n) : "memory")

__device__ __forceinline__ void ldsm_x4(uint32_t (&r)[4], uint32_t addr) {
    asm volatile("ldmatrix.sync.aligned.m8n8.x4.shared.b16 {%0,%1,%2,%3}, [%4];"
                 : "=r"(r[0]), "=r"(r[1]), "=r"(r[2]), "=r"(r[3]) : "r"(addr));
}
__device__ __forceinline__ void mma16816(
    float (&c)[4], const uint32_t (&a)[4], uint32_t b0, uint32_t b1) {
    asm volatile(
        "mma.sync.aligned.m16n8k16.row.col.f32.bf16.bf16.f32 "
        "{%0,%1,%2,%3}, {%4,%5,%6,%7}, {%8,%9}, {%0,%1,%2,%3};"
        : "+f"(c[0]), "+f"(c[1]), "+f"(c[2]), "+f"(c[3])
        : "r"(a[0]), "r"(a[1]), "r"(a[2]), "r"(a[3]), "r"(b0), "r"(b1));
}

// ---------------------------------------------------------------------------
// conversion: fp32 -> split bf16 (dedup layout)
// ---------------------------------------------------------------------------
__global__ __launch_bounds__(256) void conv_A(
    const float* __restrict__ X, const float* __restrict__ H)
{
    int f = blockIdx.x * 256 + threadIdx.x;     // float4 id, 524288 total
    int m = f >> 9;
    int k = (f & 511) * 4;
    const float* src = (k < 1024) ? (X + (size_t)m * 1024 + k)
                                  : (H + (size_t)m * 1024 + (k - 1024));
    float4 v = *reinterpret_cast<const float4*>(src);
    __nv_bfloat16 hi[4], lo[4];
    float vv[4] = {v.x, v.y, v.z, v.w};
    #pragma unroll
    for (int i = 0; i < 4; i++) {
        hi[i] = __float2bfloat16_rn(vv[i]);
        lo[i] = __float2bfloat16_rn(vv[i] - __bfloat162float(hi[i]));
    }
    size_t base = (size_t)m * KPHY + k;
    *reinterpret_cast<uint2*>(&g_A[base])        = *reinterpret_cast<uint2*>(hi);
    *reinterpret_cast<uint2*>(&g_A[base + 2048]) = *reinterpret_cast<uint2*>(lo);
}

__global__ __launch_bounds__(256) void conv_W(const float* __restrict__ W)
{
    __shared__ float tile[32][33];
    const int n0 = blockIdx.x * 32;
    const int k0 = blockIdx.y * 32;
    const int t  = threadIdx.x;
    const int tx = t & 31, ty = t >> 5;
    #pragma unroll
    for (int i = 0; i < 4; i++)
        tile[ty + 8 * i][tx] = W[(size_t)(k0 + ty + 8 * i) * NQKV + n0 + tx];
    __syncthreads();
    #pragma unroll
    for (int i = 0; i < 4; i++) {
        int nl = ty + 8 * i, kl = tx;
        float v = tile[kl][nl];
        __nv_bfloat16 hi = __float2bfloat16_rn(v);
        __nv_bfloat16 lo = __float2bfloat16_rn(v - __bfloat162float(hi));
        size_t base = (size_t)(n0 + nl) * KPHY + (k0 + kl);
        g_W[base]        = hi;
        g_W[base + 2048] = lo;
    }
}

// ---------------------------------------------------------------------------
// GEMM: g_qkv[1024,3072] = A' @ W'^T + bias    (logical K = 6144)
// CTA 128x128, BK=64, 3-stage cp.async, 8 warps (4m x 2n), warp tile 32x64.
// Stage t -> physical k:  A: t<64 ? t*64 : (t-64)*64        ([Ah|Al], Ah again)
//                         W: t<32 ? t*64 : t<64 ? (t-32)*64 : (t-64)*64+2048
// ---------------------------------------------------------------------------
__device__ __forceinline__ void load_stage(uint32_t sb, int t, int bm, int bn)
{
    const int tid = threadIdx.x;
    const uint32_t base = sb + (t % STAGES) * STAGE_BYTES;
    const int ak = (t < 64) ? t * BK : (t - 64) * BK;
    const int wk = (t < 32) ? t * BK : ((t < 64) ? (t - 32) * BK : (t - 64) * BK + 2048);
    const __nv_bfloat16* gA = g_A + ak;
    const __nv_bfloat16* gB = g_W + (size_t)bn * KPHY + wk;
    // 1024 16B-chunks per operand; 256 threads x 4 each
    #pragma unroll
    for (int i = 0; i < 4; i++) {
        int c = tid + i * 256;
        int row = c >> 3, cc = c & 7;
        cp16(base + row * PITCH + cc * 16, gA + (size_t)(bm + row) * KPHY + cc * 8);
    }
    #pragma unroll
    for (int i = 0; i < 4; i++) {
        int c = tid + i * 256;
        int row = c >> 3, cc = c & 7;
        cp16(base + TILE_B + row * PITCH + cc * 16, gB + (size_t)row * KPHY + cc * 8);
    }
    CP_COMMIT();
}

__global__ __launch_bounds__(256, 2) void gemm_qkv_mma(const float* __restrict__ bias)
{
    extern __shared__ char smem[];
    const uint32_t sb = smem_u32(smem);
    const int tid  = threadIdx.x;
    const int lane = tid & 31, wid = tid >> 5;
    const int wm = (wid & 3) * 32;
    const int wn = (wid >> 2) * 64;
    const int bn = blockIdx.x * TN;
    const int bm = blockIdx.y * TM;

    const int grp = lane >> 3;
    const int l7  = lane & 7;
    const int arow = wm + (grp & 1) * 8 + l7;
    const int achk = grp >> 1;
    const int brow = wn + (grp >> 1) * 8 + l7;
    const int bchk = grp & 1;

    float acc[2][8][4];
    #pragma unroll
    for (int i = 0; i < 2; i++)
        #pragma unroll
        for (int j = 0; j < 8; j++)
            #pragma unroll
            for (int l = 0; l < 4; l++) acc[i][j][l] = 0.0f;

    load_stage(sb, 0, bm, bn);
    load_stage(sb, 1, bm, bn);

    for (int s = 0; s < NST; s++) {
        if (s + 2 < NST) { load_stage(sb, s + 2, bm, bn); CP_WAIT(2); }
        else if (s + 1 < NST) { CP_WAIT(1); }
        else { CP_WAIT(0); }
        __syncthreads();

        const uint32_t abase = sb + (s % STAGES) * STAGE_BYTES;
        const uint32_t bbase = abase + TILE_B;

        #pragma unroll
        for (int ks = 0; ks < 4; ks++) {
            uint32_t a[2][4], b[4][4];
            #pragma unroll
            for (int mf = 0; mf < 2; mf++)
                ldsm_x4(a[mf], abase + (arow + mf * 16) * PITCH + (achk + 2 * ks) * 16);
            #pragma unroll
            for (int nf = 0; nf < 4; nf++)
                ldsm_x4(b[nf], bbase + (brow + nf * 16) * PITCH + (bchk + 2 * ks) * 16);
            #pragma unroll
            for (int mf = 0; mf < 2; mf++)
                #pragma unroll
                for (int nf = 0; nf < 4; nf++) {
                    mma16816(acc[mf][nf * 2 + 0], a[mf], b[nf][0], b[nf][1]);
                    mma16816(acc[mf][nf * 2 + 1], a[mf], b[nf][2], b[nf][3]);
                }
        }
        __syncthreads();
    }

    const int q = lane >> 2;
    const int n2 = (lane & 3) * 2;
    #pragma unroll
    for (int ng = 0; ng < 8; ng++) {
        const int gn = bn + wn + ng * 8 + n2;
        const float bx = bias[gn], by = bias[gn + 1];
        #pragma unroll
        for (int mf = 0; mf < 2; mf++) {
            const int gm = bm + wm + mf * 16 + q;
            float2 lo = { acc[mf][ng][0] + bx, acc[mf][ng][1] + by };
            float2 hi = { acc[mf][ng][2] + bx, acc[mf][ng][3] + by };
            *reinterpret_cast<float2*>(&g_qkv[(size_t)gm * NQKV + gn])       = lo;
            *reinterpret_cast<float2*>(&g_qkv[(size_t)(gm + 8) * NQKV + gn]) = hi;
        }
    }
}

// ---------------------------------------------------------------------------
// tiny w/r GEMM v2: 1 batch row per block, 8 warps, no smem.
// warp g<4: Ww cols 4g..4g+3 ; warp g>=4: Wr cols 4(g-4)..
// ---------------------------------------------------------------------------
__global__ __launch_bounds__(256) void small_gemm_wr(
    const float* __restrict__ X, const float* __restrict__ H,
    const float* __restrict__ Ww, const float* __restrict__ Wb,
    const float* __restrict__ Wr, const float* __restrict__ Rb)
{
    const int row  = blockIdx.x;
    const int tid  = threadIdx.x;
    const int warp = tid >> 5, lane = tid & 31;
    const float* Wsel = (warp < 4) ? Ww : Wr;
    const float* Bsel = (warp < 4) ? Wb : Rb;
    const int g = (warp & 3) * 4;
    const float* xr = X + (size_t)row * 1024;
    const float* hr = H + (size_t)row * 1024;

    float a0 = 0.f, a1 = 0.f, a2 = 0.f, a3 = 0.f;
    #pragma unroll 4
    for (int k = lane; k < 2048; k += 32) {
        float xv = (k < 1024) ? __ldg(xr + k) : __ldg(hr + k - 1024);
        float4 wv = *reinterpret_cast<const float4*>(&Wsel[(size_t)k * 16 + g]);
        a0 = fmaf(xv, wv.x, a0);
        a1 = fmaf(xv, wv.y, a1);
        a2 = fmaf(xv, wv.z, a2);
        a3 = fmaf(xv, wv.w, a3);
    }
    #pragma unroll
    for (int o = 16; o; o >>= 1) {
        a0 += __shfl_xor_sync(0xffffffffu, a0, o);
        a1 += __shfl_xor_sync(0xffffffffu, a1, o);
        a2 += __shfl_xor_sync(0xffffffffu, a2, o);
        a3 += __shfl_xor_sync(0xffffffffu, a3, o);
    }
    if (lane == 0) {
        const int colbase = ((warp < 4) ? 0 : 16) + g;
        float* dst = g_wr + (size_t)row * 32 + colbase;
        dst[0] = 1.0f / (1.0f + expf(-(a0 + Bsel[g + 0])));
        dst[1] = 1.0f / (1.0f + expf(-(a1 + Bsel[g + 1])));
        dst[2] = 1.0f / (1.0f + expf(-(a2 + Bsel[g + 2])));
        dst[3] = 1.0f / (1.0f + expf(-(a3 + Bsel[g + 3])));
    }
}

// ---------------------------------------------------------------------------
// per-(b,head) AM update (unchanged)
// ---------------------------------------------------------------------------
__global__ __launch_bounds__(128) void am_update(
    const float* __restrict__ AM, float* __restrict__ hout, float* __restrict__ AMout)
{
    __shared__ float AMs[64 * 65];
    __shared__ float qv[64], kv[64], vv[64], vp[64];
    __shared__ float scq, sck, kqdot;

    const int bh = blockIdx.x;
    const int b  = bh >> 4;
    const int n  = bh & 15;
    const int tid = threadIdx.x;

    const float* amg = AM + (size_t)bh * 4096;
    for (int e = tid; e < 4096; e += 128)
        AMs[(e >> 6) * 65 + (e & 63)] = amg[e];

    if (tid < 64) {
        const float* base = g_qkv + (size_t)b * NQKV + n * DHEAD + tid;
        qv[tid] = base[0];
        kv[tid] = base[1024];
        vv[tid] = base[2048];
    }
    __syncthreads();

    if (tid < 32) {
        float s = qv[tid] * qv[tid] + qv[tid + 32] * qv[tid + 32];
        #pragma unroll
        for (int o = 16; o; o >>= 1) s += __shfl_xor_sync(0xffffffffu, s, o);
        if (tid == 0) scq = 1.0f / fmaxf(sqrtf(s), 1e-12f);
    } else if (tid < 64) {
        int l = tid - 32;
        float s = kv[l] * kv[l] + kv[l + 32] * kv[l + 32];
        #pragma unroll
        for (int o = 16; o; o >>= 1) s += __shfl_xor_sync(0xffffffffu, s, o);
        if (l == 0) sck = 1.0f / fmaxf(sqrtf(s), 1e-12f);
    }
    __syncthreads();
    if (tid < 64) { qv[tid] *= scq; kv[tid] *= sck; }
    __syncthreads();
    if (tid < 32) {
        float s = kv[tid] * qv[tid] + kv[tid + 32] * qv[tid + 32];
        #pragma unroll
        for (int o = 16; o; o >>= 1) s += __shfl_xor_sync(0xffffffffu, s, o);
        if (tid == 0) kqdot = s;
    }
    __syncthreads();

    const float w = g_wr[(size_t)b * 32 + n];
    const float r = g_wr[(size_t)b * 32 + 16 + n];

    if (tid < 64) {
        const float* rowp = &AMs[tid * 65];
        float dk = 0.0f, dq = 0.0f;
        #pragma unroll 16
        for (int q = 0; q < 64; q++) {
            float a = rowp[q];
            dk = fmaf(a, kv[q], dk);
            dq = fmaf(a, qv[q], dq);
        }
        float vpv = w * (vv[tid] - dk);
        vp[tid] = vpv;
        hout[(size_t)b * 1024 + n * DHEAD + tid] = (dq + vpv * kqdot) * r;
    }
    __syncthreads();

    float* og = AMout + (size_t)bh * 4096;
    for (int e = tid; e < 4096; e += 128) {
        int v = e >> 6, q = e & 63;
        og[e] = AMs[v * 65 + q] + kv[q] * vp[v];
    }
}

// ---------------------------------------------------------------------------
extern "C" void kernel_launch(void* const* d_in, const int* in_sizes, int n_in,
                              void* d_out, int out_size)
{
    const float* x      = (const float*)d_in[0];
    const float* h      = (const float*)d_in[1];
    const float* AM     = (const float*)d_in[2];
    const float* Wqkv_w = (const float*)d_in[3];
    const float* Wqkv_b = (const float*)d_in[4];
    const float* Ww_w   = (const float*)d_in[5];
    const float* Ww_b   = (const float*)d_in[6];
    const float* Wr_w   = (const float*)d_in[7];
    const float* Wr_b   = (const float*)d_in[8];

    float* out    = (float*)d_out;
    float* h_new  = out;
    float* AM_new = out + (size_t)B_ * 1024;

    cudaFuncSetAttribute(gemm_qkv_mma,
                         cudaFuncAttributeMaxDynamicSharedMemorySize, SMEM_TOTAL);

    conv_A<<<2048, 256>>>(x, h);
    conv_W<<<dim3(NQKV / 32, K_ / 32), 256>>>(Wqkv_w);
    small_gemm_wr<<<B_, 256>>>(x, h, Ww_w, Ww_b, Wr_w, Wr_b);
    gemm_qkv_mma<<<dim3(NQKV / TN, B_ / TM), 256, SMEM_TOTAL>>>(Wqkv_b);
    am_update<<<B_ * NHEAD_, 128>>>(AM, h_new, AM_new);
}

// round 5
// speedup vs baseline: 1.3207x; 1.3207x over previous
#include <cuda_runtime.h>
#include <cuda_bf16.h>
#include <cuda_fp16.h>
#include <math.h>
#include <cstdint>

// ---------------------------------------------------------------------------
// LSAMCell — Round 5.
//   fp16 2-term split GEMM: A = Ah + Al (fp16 each, exact to ~22 bits),
//   qkv ≈ [Ah|Al] (K=4096) @ [Wh;Wh] + bias.  Missing A@Wl term ~1.4e-4 rel.
//   CTA tile 128x96 -> grid 256, occ 2: fully resident single wave.
// ---------------------------------------------------------------------------

#define B_      1024
#define NQKV    3072
#define KA      4096               // physical A' K ([Ah | Al])
#define KW      2048               // physical W  K (Wh only)
#define NHEAD_  16
#define DHEAD   64

// GEMM tiling
#define TM      128
#define TN      96
#define BK      64
#define STAGES  3
#define NST     64                 // logical 4096 / 64
#define PITCH   144                // 128B data + 16B skew (8 distinct 16B banks)
#define TILE_A  (TM * PITCH)       // 18432
#define TILE_Bz (TN * PITCH)       // 13824
#define STAGE_BYTES (TILE_A + TILE_Bz)       // 32256
#define SMEM_TOTAL  (STAGES * STAGE_BYTES)   // 96768

// device scratch (allocation-free rule)
__device__ float g_qkv[B_ * NQKV];                  // 12 MB
__device__ float g_wr [B_ * 32];
__device__ __align__(16) __half g_A[B_ * KA];       // 8 MB   [Ah | Al]
__device__ __align__(16) __half g_W[NQKV * KW];     // 12.6 MB  Wh

// ---------------------------------------------------------------------------
__device__ __forceinline__ uint32_t smem_u32(const void* p) {
    uint32_t a;
    asm("{ .reg .u64 t; cvta.to.shared.u64 t, %1; cvt.u32.u64 %0, t; }" : "=r"(a) : "l"(p));
    return a;
}
__device__ __forceinline__ void cp16(uint32_t dst, const void* src) {
    asm volatile("cp.async.cg.shared.global [%0], [%1], 16;" :: "r"(dst), "l"(src));
}
#define CP_COMMIT() asm volatile("cp.async.commit_group;" ::: "memory")
#define CP_WAIT(n)  asm volatile("cp.async.wait_group %0;" :: "n"(n) : "memory")

__device__ __forceinline__ void ldsm_x4(uint32_t (&r)[4], uint32_t addr) {
    asm volatile("ldmatrix.sync.aligned.m8n8.x4.shared.b16 {%0,%1,%2,%3}, [%4];"
                 : "=r"(r[0]), "=r"(r[1]), "=r"(r[2]), "=r"(r[3]) : "r"(addr));
}
__device__ __forceinline__ void mma16816(
    float (&c)[4], const uint32_t (&a)[4], uint32_t b0, uint32_t b1) {
    asm volatile(
        "mma.sync.aligned.m16n8k16.row.col.f32.f16.f16.f32 "
        "{%0,%1,%2,%3}, {%4,%5,%6,%7}, {%8,%9}, {%0,%1,%2,%3};"
        : "+f"(c[0]), "+f"(c[1]), "+f"(c[2]), "+f"(c[3])
        : "r"(a[0]), "r"(a[1]), "r"(a[2]), "r"(a[3]), "r"(b0), "r"(b1));
}

// ---------------------------------------------------------------------------
// conversion: fp32 -> fp16 split
// ---------------------------------------------------------------------------
__global__ __launch_bounds__(256) void conv_A(
    const float* __restrict__ X, const float* __restrict__ H)
{
    int f = blockIdx.x * 256 + threadIdx.x;     // float4 id, 524288 total
    int m = f >> 9;
    int k = (f & 511) * 4;
    const float* src = (k < 1024) ? (X + (size_t)m * 1024 + k)
                                  : (H + (size_t)m * 1024 + (k - 1024));
    float4 v = *reinterpret_cast<const float4*>(src);
    __half hi[4], lo[4];
    float vv[4] = {v.x, v.y, v.z, v.w};
    #pragma unroll
    for (int i = 0; i < 4; i++) {
        hi[i] = __float2half_rn(vv[i]);
        lo[i] = __float2half_rn(vv[i] - __half2float(hi[i]));
    }
    size_t base = (size_t)m * KA + k;
    *reinterpret_cast<uint2*>(&g_A[base])        = *reinterpret_cast<uint2*>(hi);
    *reinterpret_cast<uint2*>(&g_A[base + 2048]) = *reinterpret_cast<uint2*>(lo);
}

__global__ __launch_bounds__(256) void conv_W(const float* __restrict__ W)
{
    __shared__ float tile[32][33];
    const int n0 = blockIdx.x * 32;
    const int k0 = blockIdx.y * 32;
    const int t  = threadIdx.x;
    const int tx = t & 31, ty = t >> 5;
    #pragma unroll
    for (int i = 0; i < 4; i++)
        tile[ty + 8 * i][tx] = W[(size_t)(k0 + ty + 8 * i) * NQKV + n0 + tx];
    __syncthreads();
    #pragma unroll
    for (int i = 0; i < 4; i++) {
        int nl = ty + 8 * i, kl = tx;
        g_W[(size_t)(n0 + nl) * KW + (k0 + kl)] = __float2half_rn(tile[kl][nl]);
    }
}

// ---------------------------------------------------------------------------
// GEMM: g_qkv[1024,3072] = [Ah|Al] @ [Wh;Wh]^T + bias   (logical K=4096)
// CTA 128x96, BK=64, 3-stage cp.async, 8 warps (4m x 2n), warp tile 32x48.
// ---------------------------------------------------------------------------
__device__ __forceinline__ void load_stage(uint32_t sb, int t, int bm, int bn)
{
    const int tid = threadIdx.x;
    const uint32_t base = sb + (t % STAGES) * STAGE_BYTES;
    const int ak = t * BK;                               // direct: [Ah|Al]
    const int wk = ((t < 32) ? t : (t - 32)) * BK;       // Wh twice
    const __half* gA = g_A + ak;
    const __half* gB = g_W + wk;
    // A: 1024 chunks of 16B; 256 threads x 4
    #pragma unroll
    for (int i = 0; i < 4; i++) {
        int c = tid + i * 256;
        int row = c >> 3, cc = c & 7;
        cp16(base + row * PITCH + cc * 16, gA + (size_t)(bm + row) * KA + cc * 8);
    }
    // B: 768 chunks of 16B; 256 threads x 3
    #pragma unroll
    for (int i = 0; i < 3; i++) {
        int c = tid + i * 256;
        int row = c >> 3, cc = c & 7;
        cp16(base + TILE_A + row * PITCH + cc * 16, gB + (size_t)(bn + row) * KW + cc * 8);
    }
    CP_COMMIT();
}

__global__ __launch_bounds__(256, 2) void gemm_qkv_mma(const float* __restrict__ bias)
{
    extern __shared__ char smem[];
    const uint32_t sb = smem_u32(smem);
    const int tid  = threadIdx.x;
    const int lane = tid & 31, wid = tid >> 5;
    const int wm = (wid & 3) * 32;       // 4 m-positions
    const int wn = (wid >> 2) * 48;      // 2 n-positions
    const int bn = blockIdx.x * TN;
    const int bm = blockIdx.y * TM;

    const int grp = lane >> 3;
    const int l7  = lane & 7;
    const int arow = wm + (grp & 1) * 8 + l7;
    const int achk = grp >> 1;
    const int brow = wn + (grp >> 1) * 8 + l7;
    const int bchk = grp & 1;

    float acc[2][6][4];
    #pragma unroll
    for (int i = 0; i < 2; i++)
        #pragma unroll
        for (int j = 0; j < 6; j++)
            #pragma unroll
            for (int l = 0; l < 4; l++) acc[i][j][l] = 0.0f;

    load_stage(sb, 0, bm, bn);
    load_stage(sb, 1, bm, bn);

    for (int s = 0; s < NST; s++) {
        if (s + 2 < NST) { load_stage(sb, s + 2, bm, bn); CP_WAIT(2); }
        else if (s + 1 < NST) { CP_WAIT(1); }
        else { CP_WAIT(0); }
        __syncthreads();

        const uint32_t abase = sb + (s % STAGES) * STAGE_BYTES;
        const uint32_t bbase = abase + TILE_A;

        #pragma unroll
        for (int ks = 0; ks < 4; ks++) {
            uint32_t a[2][4], b[3][4];
            #pragma unroll
            for (int mf = 0; mf < 2; mf++)
                ldsm_x4(a[mf], abase + (arow + mf * 16) * PITCH + (achk + 2 * ks) * 16);
            #pragma unroll
            for (int nf = 0; nf < 3; nf++)
                ldsm_x4(b[nf], bbase + (brow + nf * 16) * PITCH + (bchk + 2 * ks) * 16);
            #pragma unroll
            for (int mf = 0; mf < 2; mf++)
                #pragma unroll
                for (int nf = 0; nf < 3; nf++) {
                    mma16816(acc[mf][nf * 2 + 0], a[mf], b[nf][0], b[nf][1]);
                    mma16816(acc[mf][nf * 2 + 1], a[mf], b[nf][2], b[nf][3]);
                }
        }
        __syncthreads();
    }

    const int q = lane >> 2;
    const int n2 = (lane & 3) * 2;
    #pragma unroll
    for (int ng = 0; ng < 6; ng++) {
        const int gn = bn + wn + ng * 8 + n2;
        const float bx = bias[gn], by = bias[gn + 1];
        #pragma unroll
        for (int mf = 0; mf < 2; mf++) {
            const int gm = bm + wm + mf * 16 + q;
            float2 lo = { acc[mf][ng][0] + bx, acc[mf][ng][1] + by };
            float2 hi = { acc[mf][ng][2] + bx, acc[mf][ng][3] + by };
            *reinterpret_cast<float2*>(&g_qkv[(size_t)gm * NQKV + gn])       = lo;
            *reinterpret_cast<float2*>(&g_qkv[(size_t)(gm + 8) * NQKV + gn]) = hi;
        }
    }
}

// ---------------------------------------------------------------------------
// tiny w/r GEMM: 1 batch row per block, 8 warps, no smem.
// ---------------------------------------------------------------------------
__global__ __launch_bounds__(256) void small_gemm_wr(
    const float* __restrict__ X, const float* __restrict__ H,
    const float* __restrict__ Ww, const float* __restrict__ Wb,
    const float* __restrict__ Wr, const float* __restrict__ Rb)
{
    const int row  = blockIdx.x;
    const int tid  = threadIdx.x;
    const int warp = tid >> 5, lane = tid & 31;
    const float* Wsel = (warp < 4) ? Ww : Wr;
    const float* Bsel = (warp < 4) ? Wb : Rb;
    const int g = (warp & 3) * 4;
    const float* xr = X + (size_t)row * 1024;
    const float* hr = H + (size_t)row * 1024;

    float a0 = 0.f, a1 = 0.f, a2 = 0.f, a3 = 0.f;
    #pragma unroll 4
    for (int k = lane; k < 2048; k += 32) {
        float xv = (k < 1024) ? __ldg(xr + k) : __ldg(hr + k - 1024);
        float4 wv = *reinterpret_cast<const float4*>(&Wsel[(size_t)k * 16 + g]);
        a0 = fmaf(xv, wv.x, a0);
        a1 = fmaf(xv, wv.y, a1);
        a2 = fmaf(xv, wv.z, a2);
        a3 = fmaf(xv, wv.w, a3);
    }
    #pragma unroll
    for (int o = 16; o; o >>= 1) {
        a0 += __shfl_xor_sync(0xffffffffu, a0, o);
        a1 += __shfl_xor_sync(0xffffffffu, a1, o);
        a2 += __shfl_xor_sync(0xffffffffu, a2, o);
        a3 += __shfl_xor_sync(0xffffffffu, a3, o);
    }
    if (lane == 0) {
        const int colbase = ((warp < 4) ? 0 : 16) + g;
        float* dst = g_wr + (size_t)row * 32 + colbase;
        dst[0] = 1.0f / (1.0f + expf(-(a0 + Bsel[g + 0])));
        dst[1] = 1.0f / (1.0f + expf(-(a1 + Bsel[g + 1])));
        dst[2] = 1.0f / (1.0f + expf(-(a2 + Bsel[g + 2])));
        dst[3] = 1.0f / (1.0f + expf(-(a3 + Bsel[g + 3])));
    }
}

// ---------------------------------------------------------------------------
// per-(b,head) AM update (unchanged)
// ---------------------------------------------------------------------------
__global__ __launch_bounds__(128) void am_update(
    const float* __restrict__ AM, float* __restrict__ hout, float* __restrict__ AMout)
{
    __shared__ float AMs[64 * 65];
    __shared__ float qv[64], kv[64], vv[64], vp[64];
    __shared__ float scq, sck, kqdot;

    const int bh = blockIdx.x;
    const int b  = bh >> 4;
    const int n  = bh & 15;
    const int tid = threadIdx.x;

    const float* amg = AM + (size_t)bh * 4096;
    for (int e = tid; e < 4096; e += 128)
        AMs[(e >> 6) * 65 + (e & 63)] = amg[e];

    if (tid < 64) {
        const float* base = g_qkv + (size_t)b * NQKV + n * DHEAD + tid;
        qv[tid] = base[0];
        kv[tid] = base[1024];
        vv[tid] = base[2048];
    }
    __syncthreads();

    if (tid < 32) {
        float s = qv[tid] * qv[tid] + qv[tid + 32] * qv[tid + 32];
        #pragma unroll
        for (int o = 16; o; o >>= 1) s += __shfl_xor_sync(0xffffffffu, s, o);
        if (tid == 0) scq = 1.0f / fmaxf(sqrtf(s), 1e-12f);
    } else if (tid < 64) {
        int l = tid - 32;
        float s = kv[l] * kv[l] + kv[l + 32] * kv[l + 32];
        #pragma unroll
        for (int o = 16; o; o >>= 1) s += __shfl_xor_sync(0xffffffffu, s, o);
        if (l == 0) sck = 1.0f / fmaxf(sqrtf(s), 1e-12f);
    }
    __syncthreads();
    if (tid < 64) { qv[tid] *= scq; kv[tid] *= sck; }
    __syncthreads();
    if (tid < 32) {
        float s = kv[tid] * qv[tid] + kv[tid + 32] * qv[tid + 32];
        #pragma unroll
        for (int o = 16; o; o >>= 1) s += __shfl_xor_sync(0xffffffffu, s, o);
        if (tid == 0) kqdot = s;
    }
    __syncthreads();

    const float w = g_wr[(size_t)b * 32 + n];
    const float r = g_wr[(size_t)b * 32 + 16 + n];

    if (tid < 64) {
        const float* rowp = &AMs[tid * 65];
        float dk = 0.0f, dq = 0.0f;
        #pragma unroll 16
        for (int q = 0; q < 64; q++) {
            float a = rowp[q];
            dk = fmaf(a, kv[q], dk);
            dq = fmaf(a, qv[q], dq);
        }
        float vpv = w * (vv[tid] - dk);
        vp[tid] = vpv;
        hout[(size_t)b * 1024 + n * DHEAD + tid] = (dq + vpv * kqdot) * r;
    }
    __syncthreads();

    float* og = AMout + (size_t)bh * 4096;
    for (int e = tid; e < 4096; e += 128) {
        int v = e >> 6, q = e & 63;
        og[e] = AMs[v * 65 + q] + kv[q] * vp[v];
    }
}

// ---------------------------------------------------------------------------
extern "C" void kernel_launch(void* const* d_in, const int* in_sizes, int n_in,
                              void* d_out, int out_size)
{
    const float* x      = (const float*)d_in[0];
    const float* h      = (const float*)d_in[1];
    const float* AM     = (const float*)d_in[2];
    const float* Wqkv_w = (const float*)d_in[3];
    const float* Wqkv_b = (const float*)d_in[4];
    const float* Ww_w   = (const float*)d_in[5];
    const float* Ww_b   = (const float*)d_in[6];
    const float* Wr_w   = (const float*)d_in[7];
    const float* Wr_b   = (const float*)d_in[8];

    float* out    = (float*)d_out;
    float* h_new  = out;
    float* AM_new = out + (size_t)B_ * 1024;

    cudaFuncSetAttribute(gemm_qkv_mma,
                         cudaFuncAttributeMaxDynamicSharedMemorySize, SMEM_TOTAL);

    conv_A<<<2048, 256>>>(x, h);
    conv_W<<<dim3(NQKV / 32, 2048 / 32), 256>>>(Wqkv_w);
    small_gemm_wr<<<B_, 256>>>(x, h, Ww_w, Ww_b, Wr_w, Wr_b);
    gemm_qkv_mma<<<dim3(NQKV / TN, B_ / TM), 256, SMEM_TOTAL>>>(Wqkv_b);
    am_update<<<B_ * NHEAD_, 128>>>(AM, h_new, AM_new);
}